// round 3
// baseline (speedup 1.0000x reference)
#include <cuda_runtime.h>
#include <math.h>

#define K_ANG 99
#define BB 256
#define TT 2
#define NN 8192
#define TA 16
#define NPTS 18
#define DROP_P (1.0f/64.0f)
#define PI_F 3.14159265358979323846f

__device__ float2 g_cs[BB];

// ---------------- Kernel 1: selection + per-batch (cos,sin) ----------------
// One block of 256 threads (thread b = batch b).
// Fast path: Rz preserves xy-norm, so if every constrained point has
// hypot(x,y)<=1 and eef z in [-1,1], ok[k] is true for ALL k -> idx = 0.
// Slow path: scan k in order inside the block (uniform break).
__global__ void select_cs_kernel(const float* __restrict__ pos,
                                 const float* __restrict__ naction,
                                 const float* __restrict__ angles_u,
                                 const float* __restrict__ drop_u) {
    int b = threadIdx.x;

    float2 xy[NPTS];
    float r2max = 0.0f;
    bool zok = true;
    #pragma unroll
    for (int t = 0; t < TT; t++) {
        const float* p = pos + (b * TT + t) * 3;
        float x = p[0], y = p[1], z = p[2];
        xy[t] = make_float2(x, y);
        r2max = fmaxf(r2max, x * x + y * y);
        zok = zok && (z >= -1.0f) && (z <= 1.0f);
    }
    #pragma unroll
    for (int t = 0; t < TA; t++) {
        const float* ap = naction + (b * TA + t) * 10;
        float x = ap[0], y = ap[1];
        xy[TT + t] = make_float2(x, y);
        r2max = fmaxf(r2max, x * x + y * y);
    }

    int easy = (r2max <= 1.0f && zok) ? 1 : 0;
    int idx;
    if (__syncthreads_and(easy)) {
        idx = 0;                         // every k valid -> argmax(ok) = 0
    } else {
        idx = K_ANG - 1;
        for (int k = 0; k < K_ANG; k++) {
            float du = drop_u[k * BB + b];
            float a  = angles_u[(k * BB + b) * 3 + 2] - 0.5f;
            float th = (du < DROP_P ? 0.0f : a) * PI_F;
            float s, c;
            sincosf(th, &s, &c);
            bool ok = zok;
            #pragma unroll
            for (int i = 0; i < NPTS; i++) {
                float xr = c * xy[i].x - s * xy[i].y;
                float yr = s * xy[i].x + c * xy[i].y;
                ok = ok && (xr >= -1.0f) && (xr <= 1.0f)
                        && (yr >= -1.0f) && (yr <= 1.0f);
            }
            if (__syncthreads_and(ok ? 1 : 0)) { idx = k; break; }
        }
    }

    float du = drop_u[idx * BB + b];
    float a  = angles_u[(idx * BB + b) * 3 + 2] - 0.5f;
    float th = (du < DROP_P ? 0.0f : a) * PI_F;
    float s, c;
    sincosf(th, &s, &c);
    g_cs[b] = make_float2(c, s);
}

// ---------------- small-output device helpers ----------------
__device__ __forceinline__ void do_pos_quat(int b, int t,
                                            const float* __restrict__ pos,
                                            const float* __restrict__ quat_in,
                                            float* __restrict__ out_pos,
                                            float* __restrict__ out_quat) {
    float2 cs = g_cs[b];
    float c = cs.x, s = cs.y;

    const float* p = pos + (b * TT + t) * 3;
    float x = p[0], y = p[1], z = p[2];
    out_pos[(b * TT + t) * 3 + 0] = c * x - s * y;
    out_pos[(b * TT + t) * 3 + 1] = s * x + c * y;
    out_pos[(b * TT + t) * 3 + 2] = z;

    // input quat xyzw; pytorch3d math in wxyz
    const float* q = quat_in + (b * TT + t) * 4;
    float qi = q[0], qj = q[1], qk = q[2], qr = q[3];
    float two_s = 2.0f / (qr * qr + qi * qi + qj * qj + qk * qk);
    float m00 = 1.0f - two_s * (qj * qj + qk * qk);
    float m01 = two_s * (qi * qj - qk * qr);
    float m02 = two_s * (qi * qk + qj * qr);
    float m10 = two_s * (qi * qj + qk * qr);
    float m11 = 1.0f - two_s * (qi * qi + qk * qk);
    float m12 = two_s * (qj * qk - qi * qr);
    float m20 = two_s * (qi * qk - qj * qr);
    float m21 = two_s * (qj * qk + qi * qr);
    float m22 = 1.0f - two_s * (qi * qi + qj * qj);

    float n00 = c * m00 - s * m10, n01 = c * m01 - s * m11, n02 = c * m02 - s * m12;
    float n10 = s * m00 + c * m10, n11 = s * m01 + c * m11, n12 = s * m02 + c * m12;
    float n20 = m20, n21 = m21, n22 = m22;

    float qa0 = sqrtf(fmaxf(1.0f + n00 + n11 + n22, 0.0f));
    float qa1 = sqrtf(fmaxf(1.0f + n00 - n11 - n22, 0.0f));
    float qa2 = sqrtf(fmaxf(1.0f - n00 + n11 - n22, 0.0f));
    float qa3 = sqrtf(fmaxf(1.0f - n00 - n11 + n22, 0.0f));
    int best = 0; float bv = qa0, qbest = qa0;
    if (qa1 > bv) { bv = qa1; best = 1; qbest = qa1; }
    if (qa2 > bv) { bv = qa2; best = 2; qbest = qa2; }
    if (qa3 > bv) { bv = qa3; best = 3; qbest = qa3; }
    float cw, cx, cy, cz;
    if (best == 0)      { cw = qa0 * qa0; cx = n21 - n12;  cy = n02 - n20;  cz = n10 - n01; }
    else if (best == 1) { cw = n21 - n12; cx = qa1 * qa1;  cy = n10 + n01;  cz = n02 + n20; }
    else if (best == 2) { cw = n02 - n20; cx = n10 + n01;  cy = qa2 * qa2;  cz = n12 + n21; }
    else                { cw = n10 - n01; cx = n20 + n02;  cy = n21 + n12;  cz = qa3 * qa3; }
    float d = 2.0f * fmaxf(qbest, 0.1f);
    float* oq = out_quat + (b * TT + t) * 4;
    oq[0] = cx / d; oq[1] = cy / d; oq[2] = cz / d; oq[3] = cw / d;  // xyzw
}

__device__ __forceinline__ void do_naction(int b, int t,
                                           const float* __restrict__ naction,
                                           float* __restrict__ out_na) {
    float2 cs = g_cs[b];
    float c = cs.x, s = cs.y;

    const float* na = naction + (b * TA + t) * 10;
    float x = na[0], y = na[1], z = na[2];
    float a1x = na[3], a1y = na[4], a1z = na[5];
    float a2x = na[6], a2y = na[7], a2z = na[8];
    float g = na[9];

    float n1 = sqrtf(a1x * a1x + a1y * a1y + a1z * a1z);
    float b1x = a1x / n1, b1y = a1y / n1, b1z = a1z / n1;
    float dp = b1x * a2x + b1y * a2y + b1z * a2z;
    float b2x = a2x - dp * b1x, b2y = a2y - dp * b1y, b2z = a2z - dp * b1z;
    float n2 = sqrtf(b2x * b2x + b2y * b2y + b2z * b2z);
    b2x /= n2; b2y /= n2; b2z /= n2;

    float* o = out_na + (b * TA + t) * 10;
    o[0] = c * x - s * y;
    o[1] = s * x + c * y;
    o[2] = z;
    o[3] = c * b1x - s * b2x; o[4] = c * b1y - s * b2y; o[5] = c * b1z - s * b2z;
    o[6] = s * b1x + c * b2x; o[7] = s * b1y + c * b2y; o[8] = s * b1z + c * b2z;
    o[9] = g;
}

// ---------------- Kernel 2: streaming rotation (8 pts/thread) + fused smalls ----------
__global__ void mega_kernel(const float4* __restrict__ pc,
                            float4* __restrict__ out,
                            const float* __restrict__ pos,
                            const float* __restrict__ quat_in,
                            const float* __restrict__ naction,
                            float* __restrict__ out_pos,
                            float* __restrict__ out_quat,
                            float* __restrict__ out_na) {
    int gid = blockIdx.x * blockDim.x + threadIdx.x;  // oct index (8 points)
    int b = gid >> 11;                                // 2048 octs per batch (uniform/block)
    float2 cs = g_cs[b];
    float c = cs.x, s = cs.y;

    const float4* ip = pc + (size_t)gid * 12;
    float4 f[12];
    #pragma unroll
    for (int i = 0; i < 12; i++) f[i] = __ldcs(ip + i);

    // 8 points x 6 floats. Point j: x at float 6j -> f[(6j)/4] component (6j)%4.
    float x, y;
    x = f[0].x;  y = f[0].y;  f[0].x  = c*x - s*y; f[0].y  = s*x + c*y;
    x = f[1].z;  y = f[1].w;  f[1].z  = c*x - s*y; f[1].w  = s*x + c*y;
    x = f[3].x;  y = f[3].y;  f[3].x  = c*x - s*y; f[3].y  = s*x + c*y;
    x = f[4].z;  y = f[4].w;  f[4].z  = c*x - s*y; f[4].w  = s*x + c*y;
    x = f[6].x;  y = f[6].y;  f[6].x  = c*x - s*y; f[6].y  = s*x + c*y;
    x = f[7].z;  y = f[7].w;  f[7].z  = c*x - s*y; f[7].w  = s*x + c*y;
    x = f[9].x;  y = f[9].y;  f[9].x  = c*x - s*y; f[9].y  = s*x + c*y;
    x = f[10].z; y = f[10].w; f[10].z = c*x - s*y; f[10].w = s*x + c*y;

    float4* op = out + (size_t)gid * 12;
    #pragma unroll
    for (int i = 0; i < 12; i++) __stcs(op + i, f[i]);

    // fused small outputs: tasks 0..511 = pos+quat, 512..4607 = naction
    if (gid < BB * TT + BB * TA) {
        if (gid < BB * TT) {
            do_pos_quat(gid >> 1, gid & 1, pos, quat_in, out_pos, out_quat);
        } else {
            int i = gid - BB * TT;
            do_naction(i >> 4, i & 15, naction, out_na);
        }
    }
}

extern "C" void kernel_launch(void* const* d_in, const int* in_sizes, int n_in,
                              void* d_out, int out_size) {
    const float* pc    = (const float*)d_in[0];  // (256,2,8192,6)
    const float* pos   = (const float*)d_in[1];  // (256,2,3)
    const float* quat  = (const float*)d_in[2];  // (256,2,4) xyzw
    const float* na    = (const float*)d_in[3];  // (256,16,10)
    const float* ang   = (const float*)d_in[4];  // (99,256,3)
    const float* drop  = (const float*)d_in[5];  // (99,256)

    float* out      = (float*)d_out;
    float* out_pc   = out;
    float* out_pos  = out_pc  + (size_t)BB * TT * NN * 6;
    float* out_quat = out_pos + BB * TT * 3;
    float* out_na   = out_quat + BB * TT * 4;

    select_cs_kernel<<<1, BB>>>(pos, na, ang, drop);

    int octs = BB * TT * NN / 8;                   // 524,288 threads
    mega_kernel<<<octs / 256, 256>>>((const float4*)pc, (float4*)out_pc,
                                     pos, quat, na, out_pos, out_quat, out_na);
}

// round 4
// speedup vs baseline: 1.1133x; 1.1133x over previous
#include <cuda_runtime.h>
#include <math.h>

#define K_ANG 99
#define BB 256
#define TT 2
#define NN 8192
#define TA 16
#define NPTS 18
#define DROP_P (1.0f/64.0f)
#define PI_F 3.14159265358979323846f

__device__ float2 g_cs[BB];

// ---------------- Kernel 1: selection + per-batch (cos,sin) ----------------
__global__ void select_cs_kernel(const float* __restrict__ pos,
                                 const float* __restrict__ naction,
                                 const float* __restrict__ angles_u,
                                 const float* __restrict__ drop_u) {
    int b = threadIdx.x;

    float2 xy[NPTS];
    float r2max = 0.0f;
    bool zok = true;
    #pragma unroll
    for (int t = 0; t < TT; t++) {
        const float* p = pos + (b * TT + t) * 3;
        float x = p[0], y = p[1], z = p[2];
        xy[t] = make_float2(x, y);
        r2max = fmaxf(r2max, x * x + y * y);
        zok = zok && (z >= -1.0f) && (z <= 1.0f);
    }
    #pragma unroll
    for (int t = 0; t < TA; t++) {
        const float* ap = naction + (b * TA + t) * 10;
        float x = ap[0], y = ap[1];
        xy[TT + t] = make_float2(x, y);
        r2max = fmaxf(r2max, x * x + y * y);
    }

    int easy = (r2max <= 1.0f && zok) ? 1 : 0;
    int idx;
    if (__syncthreads_and(easy)) {
        idx = 0;                         // Rz preserves xy-norm -> all k valid -> argmax = 0
    } else {
        idx = K_ANG - 1;
        for (int k = 0; k < K_ANG; k++) {
            float du = drop_u[k * BB + b];
            float a  = angles_u[(k * BB + b) * 3 + 2] - 0.5f;
            float th = (du < DROP_P ? 0.0f : a) * PI_F;
            float s, c;
            sincosf(th, &s, &c);
            bool ok = zok;
            #pragma unroll
            for (int i = 0; i < NPTS; i++) {
                float xr = c * xy[i].x - s * xy[i].y;
                float yr = s * xy[i].x + c * xy[i].y;
                ok = ok && (xr >= -1.0f) && (xr <= 1.0f)
                        && (yr >= -1.0f) && (yr <= 1.0f);
            }
            if (__syncthreads_and(ok ? 1 : 0)) { idx = k; break; }
        }
    }

    float du = drop_u[idx * BB + b];
    float a  = angles_u[(idx * BB + b) * 3 + 2] - 0.5f;
    float th = (du < DROP_P ? 0.0f : a) * PI_F;
    float s, c;
    sincosf(th, &s, &c);
    g_cs[b] = make_float2(c, s);
}

// ---------------- Kernel 2: small outputs (pos/quat/naction), PDL dependent --------
__global__ void small_kernel(const float* __restrict__ pos,
                             const float* __restrict__ quat_in,
                             const float* __restrict__ naction,
                             float* __restrict__ out_pos,
                             float* __restrict__ out_quat,
                             float* __restrict__ out_na) {
    int T = blockIdx.x * blockDim.x + threadIdx.x;

    cudaGridDependencySynchronize();   // wait for select_cs_kernel (g_cs ready)

    if (T < BB * TT) {
        int b = T >> 1, t = T & 1;
        float2 cs = g_cs[b];
        float c = cs.x, s = cs.y;

        const float* p = pos + (b * TT + t) * 3;
        float x = p[0], y = p[1], z = p[2];
        out_pos[(b * TT + t) * 3 + 0] = c * x - s * y;
        out_pos[(b * TT + t) * 3 + 1] = s * x + c * y;
        out_pos[(b * TT + t) * 3 + 2] = z;

        const float* q = quat_in + (b * TT + t) * 4;   // xyzw in, math in wxyz
        float qi = q[0], qj = q[1], qk = q[2], qr = q[3];
        float two_s = 2.0f / (qr * qr + qi * qi + qj * qj + qk * qk);
        float m00 = 1.0f - two_s * (qj * qj + qk * qk);
        float m01 = two_s * (qi * qj - qk * qr);
        float m02 = two_s * (qi * qk + qj * qr);
        float m10 = two_s * (qi * qj + qk * qr);
        float m11 = 1.0f - two_s * (qi * qi + qk * qk);
        float m12 = two_s * (qj * qk - qi * qr);
        float m20 = two_s * (qi * qk - qj * qr);
        float m21 = two_s * (qj * qk + qi * qr);
        float m22 = 1.0f - two_s * (qi * qi + qj * qj);

        float n00 = c * m00 - s * m10, n01 = c * m01 - s * m11, n02 = c * m02 - s * m12;
        float n10 = s * m00 + c * m10, n11 = s * m01 + c * m11, n12 = s * m02 + c * m12;
        float n20 = m20, n21 = m21, n22 = m22;

        float qa0 = sqrtf(fmaxf(1.0f + n00 + n11 + n22, 0.0f));
        float qa1 = sqrtf(fmaxf(1.0f + n00 - n11 - n22, 0.0f));
        float qa2 = sqrtf(fmaxf(1.0f - n00 + n11 - n22, 0.0f));
        float qa3 = sqrtf(fmaxf(1.0f - n00 - n11 + n22, 0.0f));
        int best = 0; float bv = qa0, qbest = qa0;
        if (qa1 > bv) { bv = qa1; best = 1; qbest = qa1; }
        if (qa2 > bv) { bv = qa2; best = 2; qbest = qa2; }
        if (qa3 > bv) { bv = qa3; best = 3; qbest = qa3; }
        float cw, cx, cy, cz;
        if (best == 0)      { cw = qa0 * qa0; cx = n21 - n12;  cy = n02 - n20;  cz = n10 - n01; }
        else if (best == 1) { cw = n21 - n12; cx = qa1 * qa1;  cy = n10 + n01;  cz = n02 + n20; }
        else if (best == 2) { cw = n02 - n20; cx = n10 + n01;  cy = qa2 * qa2;  cz = n12 + n21; }
        else                { cw = n10 - n01; cx = n20 + n02;  cy = n21 + n12;  cz = qa3 * qa3; }
        float d = 2.0f * fmaxf(qbest, 0.1f);
        float* oq = out_quat + (b * TT + t) * 4;
        oq[0] = cx / d; oq[1] = cy / d; oq[2] = cz / d; oq[3] = cw / d;  // xyzw
        return;
    }

    int i = T - BB * TT;
    if (i < BB * TA) {
        int b = i >> 4, t = i & 15;
        float2 cs = g_cs[b];
        float c = cs.x, s = cs.y;

        const float* na = naction + (b * TA + t) * 10;
        float x = na[0], y = na[1], z = na[2];
        float a1x = na[3], a1y = na[4], a1z = na[5];
        float a2x = na[6], a2y = na[7], a2z = na[8];
        float g = na[9];

        float n1 = sqrtf(a1x * a1x + a1y * a1y + a1z * a1z);
        float b1x = a1x / n1, b1y = a1y / n1, b1z = a1z / n1;
        float dp = b1x * a2x + b1y * a2y + b1z * a2z;
        float b2x = a2x - dp * b1x, b2y = a2y - dp * b1y, b2z = a2z - dp * b1z;
        float n2 = sqrtf(b2x * b2x + b2y * b2y + b2z * b2z);
        b2x /= n2; b2y /= n2; b2z /= n2;

        float* o = out_na + (b * TA + t) * 10;
        o[0] = c * x - s * y;
        o[1] = s * x + c * y;
        o[2] = z;
        o[3] = c * b1x - s * b2x; o[4] = c * b1y - s * b2y; o[5] = c * b1z - s * b2z;
        o[6] = s * b1x + c * b2x; o[7] = s * b1y + c * b2y; o[8] = s * b1z + c * b2z;
        o[9] = g;
    }
}

// ---------------- Kernel 3: streaming rotation, 4 pts/thread, PDL dependent --------
__global__ void __launch_bounds__(256) pc_kernel(const float4* __restrict__ pc,
                                                 float4* __restrict__ out) {
    int q = blockIdx.x * blockDim.x + threadIdx.x;   // quad index (4 points)
    const float4* ip = pc + (size_t)q * 6;

    // issue bulk loads BEFORE the grid dependency sync — DRAM latency overlaps
    // the predecessor kernels' tails
    float4 f0 = __ldcs(ip + 0);
    float4 f1 = __ldcs(ip + 1);
    float4 f2 = __ldcs(ip + 2);
    float4 f3 = __ldcs(ip + 3);
    float4 f4 = __ldcs(ip + 4);
    float4 f5 = __ldcs(ip + 5);

    cudaGridDependencySynchronize();   // g_cs now valid

    int b = q >> 12;                   // 4096 quads per batch (uniform per block)
    float2 cs = g_cs[b];
    float c = cs.x, s = cs.y;

    float x, y;
    x = f0.x; y = f0.y; f0.x = c * x - s * y; f0.y = s * x + c * y;
    x = f1.z; y = f1.w; f1.z = c * x - s * y; f1.w = s * x + c * y;
    x = f3.x; y = f3.y; f3.x = c * x - s * y; f3.y = s * x + c * y;
    x = f4.z; y = f4.w; f4.z = c * x - s * y; f4.w = s * x + c * y;

    float4* op = out + (size_t)q * 6;
    __stcs(op + 0, f0);
    __stcs(op + 1, f1);
    __stcs(op + 2, f2);
    __stcs(op + 3, f3);
    __stcs(op + 4, f4);
    __stcs(op + 5, f5);
}

extern "C" void kernel_launch(void* const* d_in, const int* in_sizes, int n_in,
                              void* d_out, int out_size) {
    const float* pc    = (const float*)d_in[0];
    const float* pos   = (const float*)d_in[1];
    const float* quat  = (const float*)d_in[2];
    const float* na    = (const float*)d_in[3];
    const float* ang   = (const float*)d_in[4];
    const float* drop  = (const float*)d_in[5];

    float* out      = (float*)d_out;
    float* out_pc   = out;
    float* out_pos  = out_pc  + (size_t)BB * TT * NN * 6;
    float* out_quat = out_pos + BB * TT * 3;
    float* out_na   = out_quat + BB * TT * 4;

    // node 1: selection (plain launch)
    select_cs_kernel<<<1, BB>>>(pos, na, ang, drop);

    // nodes 2+3: PDL dependents — launch early, sync inside
    cudaLaunchAttribute attr[1];
    attr[0].id = cudaLaunchAttributeProgrammaticStreamSerialization;
    attr[0].val.programmaticStreamSerializationAllowed = 1;

    {
        cudaLaunchConfig_t cfg = {};
        cfg.gridDim  = dim3(18, 1, 1);
        cfg.blockDim = dim3(256, 1, 1);
        cfg.dynamicSmemBytes = 0;
        cfg.stream = 0;
        cfg.attrs = attr;
        cfg.numAttrs = 1;
        cudaLaunchKernelEx(&cfg, small_kernel, pos, quat, na,
                           out_pos, out_quat, out_na);
    }
    {
        int quads = BB * TT * NN / 4;              // 1,048,576
        cudaLaunchConfig_t cfg = {};
        cfg.gridDim  = dim3(quads / 256, 1, 1);    // 4096 blocks
        cfg.blockDim = dim3(256, 1, 1);
        cfg.dynamicSmemBytes = 0;
        cfg.stream = 0;
        cfg.attrs = attr;
        cfg.numAttrs = 1;
        cudaLaunchKernelEx(&cfg, pc_kernel, (const float4*)pc, (float4*)out_pc);
    }
}

// round 5
// speedup vs baseline: 1.2697x; 1.1404x over previous
#include <cuda_runtime.h>
#include <math.h>

#define K_ANG 99
#define BB 256
#define TT 2
#define NN 8192
#define TA 16
#define NPTS 18
#define DROP_P (1.0f/64.0f)
#define PI_F 3.14159265358979323846f

__device__ float2 g_cs[BB];

// ---------------- Kernel 1: selection + per-batch (cos,sin) ----------------
// 1024 threads: 4 threads per batch b split the 18 constrained points.
// Fast path (all xy-norms <= 1 and eef |z| <= 1): ok[k] true for ALL k
// (Rz preserves xy-norm) -> idx = 0, whose inputs were preloaded -> one
// memory round total.
__global__ void __launch_bounds__(1024) select_cs_kernel(
        const float* __restrict__ pos,
        const float* __restrict__ naction,
        const float* __restrict__ angles_u,
        const float* __restrict__ drop_u) {
    __shared__ float2 s_xy[BB][NPTS];
    __shared__ int    s_zok[BB];

    int tid = threadIdx.x;
    int b = tid >> 2;
    int j = tid & 3;

    // preload k=0 inputs in parallel with the point loads
    float du0 = 0.0f, a0 = 0.0f;
    if (tid < BB) {
        du0 = drop_u[tid];
        a0  = angles_u[tid * 3 + 2];
        s_zok[tid] = 1;
    }
    __syncthreads();

    float r2max = 0.0f;
    bool zok = true;
    #pragma unroll
    for (int i = j; i < NPTS; i += 4) {
        float x, y;
        if (i < TT) {
            const float* p = pos + (b * TT + i) * 3;
            x = p[0]; y = p[1];
            float z = p[2];
            zok = zok && (z >= -1.0f) && (z <= 1.0f);
        } else {
            const float* ap = naction + (b * TA + (i - TT)) * 10;
            x = ap[0]; y = ap[1];
        }
        s_xy[b][i] = make_float2(x, y);
        r2max = fmaxf(r2max, x * x + y * y);
    }
    if (!zok) s_zok[b] = 0;   // only 0-writes race: benign

    int easy = (r2max <= 1.0f && zok) ? 1 : 0;
    if (__syncthreads_and(easy)) {
        // idx = 0, inputs already in registers
        if (tid < BB) {
            float th = (du0 < DROP_P ? 0.0f : (a0 - 0.5f)) * PI_F;
            float s, c;
            sincosf(th, &s, &c);
            g_cs[tid] = make_float2(c, s);
        }
        return;
    }

    // ---- slow path (correctness fallback) ----
    int idx = K_ANG - 1;
    for (int k = 0; k < K_ANG; k++) {
        bool ok = true;
        if (tid < BB) {
            float du = drop_u[k * BB + tid];
            float a  = angles_u[(k * BB + tid) * 3 + 2] - 0.5f;
            float th = (du < DROP_P ? 0.0f : a) * PI_F;
            float s, c;
            sincosf(th, &s, &c);
            ok = (s_zok[tid] != 0);
            #pragma unroll
            for (int i = 0; i < NPTS; i++) {
                float2 p = s_xy[tid][i];
                float xr = c * p.x - s * p.y;
                float yr = s * p.x + c * p.y;
                ok = ok && (xr >= -1.0f) && (xr <= 1.0f)
                        && (yr >= -1.0f) && (yr <= 1.0f);
            }
        }
        if (__syncthreads_and(ok ? 1 : 0)) { idx = k; break; }
    }
    if (tid < BB) {
        float du = drop_u[idx * BB + tid];
        float a  = angles_u[(idx * BB + tid) * 3 + 2] - 0.5f;
        float th = (du < DROP_P ? 0.0f : a) * PI_F;
        float s, c;
        sincosf(th, &s, &c);
        g_cs[tid] = make_float2(c, s);
    }
}

// ---------------- small-output helpers ----------------
__device__ __forceinline__ void do_pos_quat(int b, int t,
                                            const float* __restrict__ pos,
                                            const float* __restrict__ quat_in,
                                            float* __restrict__ out_pos,
                                            float* __restrict__ out_quat) {
    float2 cs = g_cs[b];
    float c = cs.x, s = cs.y;

    const float* p = pos + (b * TT + t) * 3;
    float x = p[0], y = p[1], z = p[2];
    out_pos[(b * TT + t) * 3 + 0] = c * x - s * y;
    out_pos[(b * TT + t) * 3 + 1] = s * x + c * y;
    out_pos[(b * TT + t) * 3 + 2] = z;

    const float* q = quat_in + (b * TT + t) * 4;   // xyzw in, math in wxyz
    float qi = q[0], qj = q[1], qk = q[2], qr = q[3];
    float two_s = 2.0f / (qr * qr + qi * qi + qj * qj + qk * qk);
    float m00 = 1.0f - two_s * (qj * qj + qk * qk);
    float m01 = two_s * (qi * qj - qk * qr);
    float m02 = two_s * (qi * qk + qj * qr);
    float m10 = two_s * (qi * qj + qk * qr);
    float m11 = 1.0f - two_s * (qi * qi + qk * qk);
    float m12 = two_s * (qj * qk - qi * qr);
    float m20 = two_s * (qi * qk - qj * qr);
    float m21 = two_s * (qj * qk + qi * qr);
    float m22 = 1.0f - two_s * (qi * qi + qj * qj);

    float n00 = c * m00 - s * m10, n01 = c * m01 - s * m11, n02 = c * m02 - s * m12;
    float n10 = s * m00 + c * m10, n11 = s * m01 + c * m11, n12 = s * m02 + c * m12;
    float n20 = m20, n21 = m21, n22 = m22;

    float qa0 = sqrtf(fmaxf(1.0f + n00 + n11 + n22, 0.0f));
    float qa1 = sqrtf(fmaxf(1.0f + n00 - n11 - n22, 0.0f));
    float qa2 = sqrtf(fmaxf(1.0f - n00 + n11 - n22, 0.0f));
    float qa3 = sqrtf(fmaxf(1.0f - n00 - n11 + n22, 0.0f));
    int best = 0; float bv = qa0, qbest = qa0;
    if (qa1 > bv) { bv = qa1; best = 1; qbest = qa1; }
    if (qa2 > bv) { bv = qa2; best = 2; qbest = qa2; }
    if (qa3 > bv) { bv = qa3; best = 3; qbest = qa3; }
    float cw, cx, cy, cz;
    if (best == 0)      { cw = qa0 * qa0; cx = n21 - n12;  cy = n02 - n20;  cz = n10 - n01; }
    else if (best == 1) { cw = n21 - n12; cx = qa1 * qa1;  cy = n10 + n01;  cz = n02 + n20; }
    else if (best == 2) { cw = n02 - n20; cx = n10 + n01;  cy = qa2 * qa2;  cz = n12 + n21; }
    else                { cw = n10 - n01; cx = n20 + n02;  cy = n21 + n12;  cz = qa3 * qa3; }
    float d = 2.0f * fmaxf(qbest, 0.1f);
    float* oq = out_quat + (b * TT + t) * 4;
    oq[0] = cx / d; oq[1] = cy / d; oq[2] = cz / d; oq[3] = cw / d;  // xyzw
}

__device__ __forceinline__ void do_naction(int b, int t,
                                           const float* __restrict__ naction,
                                           float* __restrict__ out_na) {
    float2 cs = g_cs[b];
    float c = cs.x, s = cs.y;

    const float* na = naction + (b * TA + t) * 10;
    float x = na[0], y = na[1], z = na[2];
    float a1x = na[3], a1y = na[4], a1z = na[5];
    float a2x = na[6], a2y = na[7], a2z = na[8];
    float g = na[9];

    float n1 = sqrtf(a1x * a1x + a1y * a1y + a1z * a1z);
    float b1x = a1x / n1, b1y = a1y / n1, b1z = a1z / n1;
    float dp = b1x * a2x + b1y * a2y + b1z * a2z;
    float b2x = a2x - dp * b1x, b2y = a2y - dp * b1y, b2z = a2z - dp * b1z;
    float n2 = sqrtf(b2x * b2x + b2y * b2y + b2z * b2z);
    b2x /= n2; b2y /= n2; b2z /= n2;

    float* o = out_na + (b * TA + t) * 10;
    o[0] = c * x - s * y;
    o[1] = s * x + c * y;
    o[2] = z;
    o[3] = c * b1x - s * b2x; o[4] = c * b1y - s * b2y; o[5] = c * b1z - s * b2z;
    o[6] = s * b1x + c * b2x; o[7] = s * b1y + c * b2y; o[8] = s * b1z + c * b2z;
    o[9] = g;
}

// ---------------- Kernel 2: streaming rotation + fused smalls, PDL ----------------
__global__ void __launch_bounds__(256) pc_kernel(const float4* __restrict__ pc,
                                                 float4* __restrict__ out,
                                                 const float* __restrict__ pos,
                                                 const float* __restrict__ quat_in,
                                                 const float* __restrict__ naction,
                                                 float* __restrict__ out_pos,
                                                 float* __restrict__ out_quat,
                                                 float* __restrict__ out_na) {
    int q = blockIdx.x * blockDim.x + threadIdx.x;   // quad index (4 points)
    const float4* ip = pc + (size_t)q * 6;

    // bulk loads BEFORE the dependency sync: DRAM latency overlaps select
    float4 f0 = __ldcs(ip + 0);
    float4 f1 = __ldcs(ip + 1);
    float4 f2 = __ldcs(ip + 2);
    float4 f3 = __ldcs(ip + 3);
    float4 f4 = __ldcs(ip + 4);
    float4 f5 = __ldcs(ip + 5);

    cudaGridDependencySynchronize();   // g_cs now valid

    int b = blockIdx.x >> 4;           // 16 blocks per batch: uniform index
    float2 cs = g_cs[b];
    float c = cs.x, s = cs.y;

    float x, y;
    x = f0.x; y = f0.y; f0.x = c * x - s * y; f0.y = s * x + c * y;
    x = f1.z; y = f1.w; f1.z = c * x - s * y; f1.w = s * x + c * y;
    x = f3.x; y = f3.y; f3.x = c * x - s * y; f3.y = s * x + c * y;
    x = f4.z; y = f4.w; f4.z = c * x - s * y; f4.w = s * x + c * y;

    float4* op = out + (size_t)q * 6;
    __stcs(op + 0, f0);
    __stcs(op + 1, f1);
    __stcs(op + 2, f2);
    __stcs(op + 3, f3);
    __stcs(op + 4, f4);
    __stcs(op + 5, f5);

    // fused small outputs (first 4608 threads)
    if (q < BB * TT + BB * TA) {
        if (q < BB * TT) {
            do_pos_quat(q >> 1, q & 1, pos, quat_in, out_pos, out_quat);
        } else {
            int i = q - BB * TT;
            do_naction(i >> 4, i & 15, naction, out_na);
        }
    }
}

extern "C" void kernel_launch(void* const* d_in, const int* in_sizes, int n_in,
                              void* d_out, int out_size) {
    const float* pc    = (const float*)d_in[0];
    const float* pos   = (const float*)d_in[1];
    const float* quat  = (const float*)d_in[2];
    const float* na    = (const float*)d_in[3];
    const float* ang   = (const float*)d_in[4];
    const float* drop  = (const float*)d_in[5];

    float* out      = (float*)d_out;
    float* out_pc   = out;
    float* out_pos  = out_pc  + (size_t)BB * TT * NN * 6;
    float* out_quat = out_pos + BB * TT * 3;
    float* out_na   = out_quat + BB * TT * 4;

    select_cs_kernel<<<1, 1024>>>(pos, na, ang, drop);

    cudaLaunchAttribute attr[1];
    attr[0].id = cudaLaunchAttributeProgrammaticStreamSerialization;
    attr[0].val.programmaticStreamSerializationAllowed = 1;

    int quads = BB * TT * NN / 4;              // 1,048,576
    cudaLaunchConfig_t cfg = {};
    cfg.gridDim  = dim3(quads / 256, 1, 1);    // 4096 blocks
    cfg.blockDim = dim3(256, 1, 1);
    cfg.dynamicSmemBytes = 0;
    cfg.stream = 0;
    cfg.attrs = attr;
    cfg.numAttrs = 1;
    cudaLaunchKernelEx(&cfg, pc_kernel, (const float4*)pc, (float4*)out_pc,
                       pos, quat, na, out_pos, out_quat, out_na);
}